// round 2
// baseline (speedup 1.0000x reference)
#include <cuda_runtime.h>
#include <math.h>

// Problem constants
#define B_    16
#define CIN   512
#define COUT  512
#define H_    32
#define HW    1024          // 32*32
#define NTOT  16384         // B_*HW
#define MTOT  4608          // 9*COUT
#define OH    64
#define OHW   4096          // 64*64

// ---- device scratch (no allocations allowed) ----
__device__ float g_style[B_ * CIN];        // [b][ci]
__device__ float g_dcoef[B_ * COUT];       // [b][co]
__device__ float g_wsq[CIN * COUT];        // [ci][co]  sum_k w^2
__device__ float g_Wt[CIN * MTOT];         // [ci][(t*512+co)]   (K-major A for GEMM)
__device__ float g_X[CIN * NTOT];          // [ci][(b*1024+hw)]
__device__ float g_C[(size_t)MTOT * NTOT]; // [(t*512+co)][(b*1024+hw)]  ~302MB

// FIR/phase mixing coefficients, indexed AA(phi, o, k) with o = 1 - d
// (d = tap-plane spatial offset). Derived from f=[0.25,0.75,0.75,0.25]
// and conv_transpose relation y1[2i+k] += w[k]*x[i].
__device__ __forceinline__ float AA(int phi, int o, int ki) {
    constexpr float tab[2][3][3] = {
        {{0.25f, 0.00f, 0.00f},
         {0.75f, 0.75f, 0.25f},
         {0.00f, 0.25f, 0.75f}},
        {{0.75f, 0.25f, 0.00f},
         {0.25f, 0.75f, 0.75f},
         {0.00f, 0.00f, 0.25f}}
    };
    return tab[phi][o][ki];
}

// ---------------------------------------------------------------------------
// 1) style[b,ci] = (w_latent[b] . affine_weight[ci]) / sqrt(512) + affine_bias[ci]
__global__ void style_kernel(const float* __restrict__ wl,
                             const float* __restrict__ aw,
                             const float* __restrict__ ab) {
    int b = blockIdx.x;
    __shared__ float sw[CIN];
    for (int i = threadIdx.x; i < CIN; i += blockDim.x) sw[i] = wl[b * CIN + i];
    __syncthreads();
    int warp = threadIdx.x >> 5, lane = threadIdx.x & 31;
    for (int ci = warp; ci < CIN; ci += 16) {
        float acc = 0.f;
        const float* row = aw + (size_t)ci * CIN;
        #pragma unroll 4
        for (int d = lane; d < CIN; d += 32) acc += sw[d] * row[d];
        #pragma unroll
        for (int off = 16; off; off >>= 1) acc += __shfl_xor_sync(0xffffffffu, acc, off);
        if (lane == 0)
            g_style[b * CIN + ci] = acc * 0.04419417382415922f + ab[ci];
    }
}

// ---------------------------------------------------------------------------
// 2) per-(co,ci): wsq + reorganize conv weight into K-major A matrix
__global__ void prep_w_kernel(const float* __restrict__ cw) {
    int co = blockIdx.x;
    int ci = threadIdx.x;
    const float* wp = cw + ((size_t)co * CIN + ci) * 9;
    float w[9];
    float q = 0.f;
    #pragma unroll
    for (int t = 0; t < 9; t++) { w[t] = wp[t]; q += w[t] * w[t]; }
    g_wsq[ci * COUT + co] = q;
    #pragma unroll
    for (int t = 0; t < 9; t++)
        g_Wt[(size_t)ci * MTOT + t * COUT + co] = w[t];
}

// ---------------------------------------------------------------------------
// 3) dcoef[b,co] = rsqrt( sum_ci style^2 * wsq[ci,co] + 1e-8 )
__global__ void dcoef_kernel() {
    int b = blockIdx.x;
    int co = threadIdx.x;
    __shared__ float s2[CIN];
    for (int i = threadIdx.x; i < CIN; i += blockDim.x) {
        float s = g_style[b * CIN + i];
        s2[i] = s * s;
    }
    __syncthreads();
    float acc = 0.f;
    #pragma unroll 4
    for (int ci = 0; ci < CIN; ci++) acc += s2[ci] * g_wsq[ci * COUT + co];
    g_dcoef[b * COUT + co] = rsqrtf(acc + 1e-8f);
}

// ---------------------------------------------------------------------------
// 4) X[ci][(b,hw)] = x[b][ci][hw] * style[b,ci]   (modulation on activations)
__global__ void modx_kernel(const float* __restrict__ x) {
    int ci = blockIdx.x, b = blockIdx.y;
    float s = g_style[b * CIN + ci];
    const float4* src = (const float4*)(x + ((size_t)b * CIN + ci) * HW);
    float4* dst = (float4*)(g_X + (size_t)ci * NTOT + b * HW);
    float4 v = src[threadIdx.x];
    v.x *= s; v.y *= s; v.z *= s; v.w *= s;
    dst[threadIdx.x] = v;
}

// ---------------------------------------------------------------------------
// 5) GEMM: C[m][n] = sum_k Wt[k][m] * X[k][n],  M=4608 N=16384 K=512
#define BM 128
#define BN 128
#define BK 16
__global__ __launch_bounds__(256) void gemm_kernel() {
    __shared__ float As[BK][BM];
    __shared__ float Bs[BK][BN];
    int m0 = blockIdx.y * BM;
    int n0 = blockIdx.x * BN;
    int tid = threadIdx.x;
    int ty = tid >> 4, tx = tid & 15;   // 16x16 thread grid, 8x8 each
    float acc[8][8] = {};

    for (int k0 = 0; k0 < CIN; k0 += BK) {
        #pragma unroll
        for (int it = 0; it < 2; it++) {
            int t2 = tid * 2 + it;           // 512 float4 loads per tile
            int kk = t2 >> 5, mv = t2 & 31;
            float4 va = *(const float4*)&g_Wt[(size_t)(k0 + kk) * MTOT + m0 + mv * 4];
            *(float4*)&As[kk][mv * 4] = va;
            float4 vb = *(const float4*)&g_X[(size_t)(k0 + kk) * NTOT + n0 + mv * 4];
            *(float4*)&Bs[kk][mv * 4] = vb;
        }
        __syncthreads();
        #pragma unroll
        for (int kk = 0; kk < BK; kk++) {
            float a[8], bb[8];
            #pragma unroll
            for (int i = 0; i < 8; i++) a[i] = As[kk][ty * 8 + i];
            #pragma unroll
            for (int j = 0; j < 8; j++) bb[j] = Bs[kk][tx * 8 + j];
            #pragma unroll
            for (int i = 0; i < 8; i++)
                #pragma unroll
                for (int j = 0; j < 8; j++)
                    acc[i][j] += a[i] * bb[j];
        }
        __syncthreads();
    }
    #pragma unroll
    for (int i = 0; i < 8; i++) {
        float* crow = g_C + (size_t)(m0 + ty * 8 + i) * NTOT + n0 + tx * 8;
        #pragma unroll
        for (int j = 0; j < 8; j += 4)
            *(float4*)&crow[j] = make_float4(acc[i][j], acc[i][j+1], acc[i][j+2], acc[i][j+3]);
    }
}

// ---------------------------------------------------------------------------
// 6) fuse: assemble upsample+FIR from tap planes, apply d, noise, bias, lrelu, clamp
__global__ __launch_bounds__(256) void fuse_kernel(const float* __restrict__ noise,
                                                   const float* __restrict__ ns_p,
                                                   const float* __restrict__ bias,
                                                   float* __restrict__ out) {
    int co = blockIdx.x, b = blockIdx.y;
    __shared__ float Cs[9][34][34];   // padded (+1 halo each side), ~41.6KB

    const size_t cbase = (size_t)b * HW;
    #pragma unroll
    for (int t = 0; t < 9; t++) {
        const float* cp = g_C + (size_t)(t * COUT + co) * NTOT + cbase;
        for (int idx = threadIdx.x; idx < 34 * 34; idx += 256) {
            int i = idx / 34 - 1, j = idx % 34 - 1;
            float v = 0.f;
            if ((unsigned)i < 32u && (unsigned)j < 32u) v = cp[i * 32 + j];
            Cs[t][idx / 34][idx % 34] = v;
        }
    }
    __syncthreads();

    int bi = threadIdx.x >> 4, bj = threadIdx.x & 15;  // 16x16 blocks of 4x4 out px
    float acc[4][4] = {};

    #pragma unroll
    for (int t = 0; t < 9; t++) {
        int ki = t / 3, kj = t % 3;
        float c[4][4];
        #pragma unroll
        for (int r = 0; r < 4; r++)
            #pragma unroll
            for (int cc = 0; cc < 4; cc++)
                c[r][cc] = Cs[t][2 * bi + r][2 * bj + cc];
        #pragma unroll
        for (int pi = 0; pi < 4; pi++) {
            int di = pi >> 1, phi = pi & 1;
            #pragma unroll
            for (int pj = 0; pj < 4; pj++) {
                int dj = pj >> 1, psi = pj & 1;
                #pragma unroll
                for (int oi = 0; oi < 3; oi++) {
                    float ai = AA(phi, oi, ki);
                    if (ai == 0.f) continue;
                    #pragma unroll
                    for (int oj = 0; oj < 3; oj++) {
                        float aj = AA(psi, oj, kj);
                        if (aj == 0.f) continue;
                        acc[pi][pj] += (ai * aj) * c[di + 2 - oi][dj + 2 - oj];
                    }
                }
            }
        }
    }

    float dval = g_dcoef[b * COUT + co];
    float ns = ns_p[0];
    float bv = bias[co];
    const float* np = noise + (size_t)b * OHW;
    float* op = out + ((size_t)b * COUT + co) * OHW;

    #pragma unroll
    for (int pi = 0; pi < 4; pi++) {
        int P = 4 * bi + pi;
        #pragma unroll
        for (int pj = 0; pj < 4; pj++) {
            int Q = 4 * bj + pj;
            float v = acc[pi][pj] * dval + np[P * OH + Q] * ns + bv;
            v = (v > 0.f) ? v : 0.2f * v;
            v *= 1.4142135623730951f;
            v = fminf(fmaxf(v, -256.f), 256.f);
            op[P * OH + Q] = v;
        }
    }
}

// ---------------------------------------------------------------------------
extern "C" void kernel_launch(void* const* d_in, const int* in_sizes, int n_in,
                              void* d_out, int out_size) {
    const float* x      = (const float*)d_in[0];   // [16,512,32,32]
    const float* wl     = (const float*)d_in[1];   // [16,512]
    const float* aw     = (const float*)d_in[2];   // [512,512]
    const float* ab     = (const float*)d_in[3];   // [512]
    const float* cw     = (const float*)d_in[4];   // [512,512,3,3]
    const float* noise  = (const float*)d_in[5];   // [16,1,64,64]
    const float* ns     = (const float*)d_in[6];   // [1]
    const float* bias   = (const float*)d_in[7];   // [512]
    float* out = (float*)d_out;                    // [16,512,64,64]

    style_kernel<<<B_, 512>>>(wl, aw, ab);
    prep_w_kernel<<<COUT, CIN>>>(cw);
    dcoef_kernel<<<B_, COUT>>>();
    modx_kernel<<<dim3(CIN, B_), 256>>>(x);
    gemm_kernel<<<dim3(NTOT / BN, MTOT / BM), 256>>>();
    fuse_kernel<<<dim3(COUT, B_), 256>>>(noise, ns, bias, out);
}

// round 7
// speedup vs baseline: 1.6690x; 1.6690x over previous
#include <cuda_runtime.h>
#include <cuda_bf16.h>
#include <math.h>
#include <stdint.h>

// Problem constants
#define B_    16
#define CIN   512
#define COUT  512
#define HW    1024          // 32*32
#define NTOT  16384         // B_*HW
#define MTOT  4608          // 9*COUT
#define OH    64
#define OHW   4096          // 64*64
#define KX    1536          // 3 * CIN (split-bf16 folded into K)

// GEMM tiling
#define BM 128
#define BN 128
#define BKE 32              // k elements per stage
#define SROW 40             // smem row stride in bf16 elements (80 bytes)
#define KSTEPS (KX / BKE)   // 48

// ---- device scratch (no allocations allowed) ----
__device__ float g_style[B_ * CIN];
__device__ float g_dcoef[B_ * COUT];
__device__ float g_wsq[CIN * COUT];
__device__ __align__(256) __nv_bfloat16 g_A[(size_t)MTOT * KX];   // [m][k']
__device__ __align__(256) __nv_bfloat16 g_B[(size_t)NTOT * KX];   // [n][k']
__device__ __align__(256) float g_C[(size_t)MTOT * NTOT];         // ~302MB

// ---------------- helpers ----------------
__device__ __forceinline__ uint32_t smem_u32(const void* p) {
    uint32_t a;
    asm("{ .reg .u64 t; cvta.to.shared.u64 t, %1; cvt.u32.u64 %0, t; }" : "=r"(a) : "l"(p));
    return a;
}

#define LDSM_X4(r, addr) \
    asm volatile("ldmatrix.sync.aligned.m8n8.x4.shared.b16 {%0,%1,%2,%3}, [%4];" \
        : "=r"((r)[0]), "=r"((r)[1]), "=r"((r)[2]), "=r"((r)[3]) : "r"(addr))

#define MMA16816(c, a, b0v, b1v) \
    asm volatile("mma.sync.aligned.m16n8k16.row.col.f32.bf16.bf16.f32 " \
        "{%0,%1,%2,%3},{%4,%5,%6,%7},{%8,%9},{%0,%1,%2,%3};" \
        : "+f"((c)[0]), "+f"((c)[1]), "+f"((c)[2]), "+f"((c)[3]) \
        : "r"((a)[0]), "r"((a)[1]), "r"((a)[2]), "r"((a)[3]), "r"(b0v), "r"(b1v))

// FIR/phase mixing coefficients (see derivation in R1)
__device__ __forceinline__ float AA(int phi, int o, int ki) {
    const float tab[2][3][3] = {
        {{0.25f, 0.00f, 0.00f},
         {0.75f, 0.75f, 0.25f},
         {0.00f, 0.25f, 0.75f}},
        {{0.75f, 0.25f, 0.00f},
         {0.25f, 0.75f, 0.75f},
         {0.00f, 0.00f, 0.25f}}
    };
    return tab[phi][o][ki];
}

// ---------------------------------------------------------------------------
// 1) style[b,ci]
__global__ void style_kernel(const float* __restrict__ wl,
                             const float* __restrict__ aw,
                             const float* __restrict__ ab) {
    int b = blockIdx.x;
    __shared__ float sw[CIN];
    for (int i = threadIdx.x; i < CIN; i += blockDim.x) sw[i] = wl[b * CIN + i];
    __syncthreads();
    int warp = threadIdx.x >> 5, lane = threadIdx.x & 31;
    for (int ci = warp; ci < CIN; ci += 16) {
        float acc = 0.f;
        const float* row = aw + (size_t)ci * CIN;
        #pragma unroll 4
        for (int d = lane; d < CIN; d += 32) acc += sw[d] * row[d];
        #pragma unroll
        for (int off = 16; off; off >>= 1) acc += __shfl_xor_sync(0xffffffffu, acc, off);
        if (lane == 0)
            g_style[b * CIN + ci] = acc * 0.04419417382415922f + ab[ci];
    }
}

// ---------------------------------------------------------------------------
// 2) weights: wsq + split-bf16 A' = [Ahi | Ahi | Alo] along K
__global__ void prep_w_kernel(const float* __restrict__ cw) {
    int co = blockIdx.x;
    int ci = threadIdx.x;
    const float* wp = cw + ((size_t)co * CIN + ci) * 9;
    float w[9];
    float q = 0.f;
    #pragma unroll
    for (int t = 0; t < 9; t++) { w[t] = wp[t]; q += w[t] * w[t]; }
    g_wsq[ci * COUT + co] = q;
    #pragma unroll
    for (int t = 0; t < 9; t++) {
        size_t m = (size_t)(t * COUT + co);
        __nv_bfloat16 hi = __float2bfloat16(w[t]);
        __nv_bfloat16 lo = __float2bfloat16(w[t] - __bfloat162float(hi));
        g_A[m * KX + ci] = hi;
        g_A[m * KX + CIN + ci] = hi;
        g_A[m * KX + 2 * CIN + ci] = lo;
    }
}

// ---------------------------------------------------------------------------
// 3) dcoef
__global__ void dcoef_kernel() {
    int b = blockIdx.x;
    int co = threadIdx.x;
    __shared__ float s2[CIN];
    for (int i = threadIdx.x; i < CIN; i += blockDim.x) {
        float s = g_style[b * CIN + i];
        s2[i] = s * s;
    }
    __syncthreads();
    float acc = 0.f;
    #pragma unroll 4
    for (int ci = 0; ci < CIN; ci++) acc += s2[ci] * g_wsq[ci * COUT + co];
    g_dcoef[b * COUT + co] = rsqrtf(acc + 1e-8f);
}

// ---------------------------------------------------------------------------
// 4) modulate + transpose + split: B' = [Bhi | Blo | Bhi] along K
// grid: (CIN/32, HW/32, B_), block: 32x8
__global__ void modx_t_kernel(const float* __restrict__ x) {
    __shared__ float tile[32][33];
    int ci0 = blockIdx.x * 32, hw0 = blockIdx.y * 32, b = blockIdx.z;
    int tx = threadIdx.x, ty = threadIdx.y;
    #pragma unroll
    for (int r = 0; r < 4; r++) {
        int ci = ci0 + ty + r * 8;
        float s = g_style[b * CIN + ci];
        tile[ty + r * 8][tx] = x[((size_t)b * CIN + ci) * HW + hw0 + tx] * s;
    }
    __syncthreads();
    #pragma unroll
    for (int r = 0; r < 4; r++) {
        int hw = hw0 + ty + r * 8;
        float v = tile[tx][ty + r * 8];
        __nv_bfloat16 hi = __float2bfloat16(v);
        __nv_bfloat16 lo = __float2bfloat16(v - __bfloat162float(hi));
        size_t n = (size_t)(b * HW + hw);
        int ci = ci0 + tx;
        g_B[n * KX + ci] = hi;
        g_B[n * KX + CIN + ci] = lo;
        g_B[n * KX + 2 * CIN + ci] = hi;
    }
}

// ---------------------------------------------------------------------------
// 5) GEMM via mma.sync m16n8k16 bf16: C[m][n] = sum_k A'[m][k]*B'[n][k]
__global__ __launch_bounds__(256, 1) void gemm_mma_kernel() {
    __shared__ __align__(128) __nv_bfloat16 sA[2][BM * SROW];
    __shared__ __align__(128) __nv_bfloat16 sB[2][BN * SROW];

    int tid = threadIdx.x, wid = tid >> 5, lane = tid & 31;
    int m0 = blockIdx.y * BM, n0 = blockIdx.x * BN;
    int wm = wid & 1, wn = wid >> 1;   // 2 (M) x 4 (N) warps

    float acc[4][4][4];
    #pragma unroll
    for (int i = 0; i < 4; i++)
        #pragma unroll
        for (int j = 0; j < 4; j++)
            #pragma unroll
            for (int q = 0; q < 4; q++) acc[i][j][q] = 0.f;

    auto load_stage = [&](int stg, int ks) {
        uint32_t aB = smem_u32(sA[stg]);
        uint32_t bB = smem_u32(sB[stg]);
        int k0 = ks * BKE;
        #pragma unroll
        for (int i = 0; i < 4; i++) {
            int u = tid + 256 * i;
            const __nv_bfloat16* src;
            uint32_t dst;
            if (u < 512) {
                int r = u >> 2, c = u & 3;
                src = g_A + (size_t)(m0 + r) * KX + k0 + c * 8;
                dst = aB + r * 80 + c * 16;
            } else {
                int v = u - 512;
                int r = v >> 2, c = v & 3;
                src = g_B + (size_t)(n0 + r) * KX + k0 + c * 8;
                dst = bB + r * 80 + c * 16;
            }
            asm volatile("cp.async.cg.shared.global [%0], [%1], 16;" :: "r"(dst), "l"(src) : "memory");
        }
        asm volatile("cp.async.commit_group;" ::: "memory");
    };

    load_stage(0, 0);

    for (int s = 0; s < KSTEPS; s++) {
        asm volatile("cp.async.wait_group 0;" ::: "memory");
        __syncthreads();
        if (s + 1 < KSTEPS) load_stage((s + 1) & 1, s + 1);

        uint32_t aB = smem_u32(sA[s & 1]);
        uint32_t bB = smem_u32(sB[s & 1]);
        #pragma unroll
        for (int kh = 0; kh < 2; kh++) {
            uint32_t a[4][4], bfr[2][4];
            #pragma unroll
            for (int mf = 0; mf < 4; mf++) {
                int row = wm * 64 + mf * 16 + (lane & 15);
                uint32_t addr = aB + row * 80 + kh * 32 + (lane >> 4) * 16;
                LDSM_X4(a[mf], addr);
            }
            #pragma unroll
            for (int ng = 0; ng < 2; ng++) {
                int row = wn * 32 + ng * 16 + (lane & 15);
                uint32_t addr = bB + row * 80 + kh * 32 + (lane >> 4) * 16;
                LDSM_X4(bfr[ng], addr);
            }
            #pragma unroll
            for (int mf = 0; mf < 4; mf++)
                #pragma unroll
                for (int nf = 0; nf < 4; nf++) {
                    uint32_t b0v = bfr[nf >> 1][nf & 1];
                    uint32_t b1v = bfr[nf >> 1][(nf & 1) + 2];
                    MMA16816(acc[mf][nf], a[mf], b0v, b1v);
                }
        }
    }

    // epilogue: write C
    #pragma unroll
    for (int mf = 0; mf < 4; mf++) {
        int mrow = m0 + wm * 64 + mf * 16 + (lane >> 2);
        #pragma unroll
        for (int nf = 0; nf < 4; nf++) {
            int ncol = n0 + wn * 32 + nf * 8 + (lane & 3) * 2;
            *(float2*)(g_C + (size_t)mrow * NTOT + ncol) =
                make_float2(acc[mf][nf][0], acc[mf][nf][1]);
            *(float2*)(g_C + (size_t)(mrow + 8) * NTOT + ncol) =
                make_float2(acc[mf][nf][2], acc[mf][nf][3]);
        }
    }
}

// ---------------------------------------------------------------------------
// 6) fuse: FIR assembly + dcoef + noise + bias + lrelu + clamp
__global__ __launch_bounds__(256) void fuse_kernel(const float* __restrict__ noise,
                                                   const float* __restrict__ ns_p,
                                                   const float* __restrict__ bias,
                                                   float* __restrict__ out) {
    int co = blockIdx.x, b = blockIdx.y;
    __shared__ float Cs[9][34][34];

    const size_t cbase = (size_t)b * HW;
    #pragma unroll
    for (int t = 0; t < 9; t++) {
        const float* cp = g_C + (size_t)(t * COUT + co) * NTOT + cbase;
        for (int idx = threadIdx.x; idx < 34 * 34; idx += 256) {
            int i = idx / 34 - 1, j = idx % 34 - 1;
            float v = 0.f;
            if ((unsigned)i < 32u && (unsigned)j < 32u) v = cp[i * 32 + j];
            Cs[t][idx / 34][idx % 34] = v;
        }
    }
    __syncthreads();

    int bi = threadIdx.x >> 4, bj = threadIdx.x & 15;
    float acc[4][4] = {};

    #pragma unroll
    for (int t = 0; t < 9; t++) {
        int ki = t / 3, kj = t % 3;
        float c[4][4];
        #pragma unroll
        for (int r = 0; r < 4; r++)
            #pragma unroll
            for (int cc = 0; cc < 4; cc++)
                c[r][cc] = Cs[t][2 * bi + r][2 * bj + cc];
        #pragma unroll
        for (int pi = 0; pi < 4; pi++) {
            int di = pi >> 1, phi = pi & 1;
            #pragma unroll
            for (int pj = 0; pj < 4; pj++) {
                int dj = pj >> 1, psi = pj & 1;
                #pragma unroll
                for (int oi = 0; oi < 3; oi++) {
                    float ai = AA(phi, oi, ki);
                    if (ai == 0.f) continue;
                    #pragma unroll
                    for (int oj = 0; oj < 3; oj++) {
                        float aj = AA(psi, oj, kj);
                        if (aj == 0.f) continue;
                        acc[pi][pj] += (ai * aj) * c[di + 2 - oi][dj + 2 - oj];
                    }
                }
            }
        }
    }

    float dval = g_dcoef[b * COUT + co];
    float ns = ns_p[0];
    float bv = bias[co];
    const float* np = noise + (size_t)b * OHW;
    float* op = out + ((size_t)b * COUT + co) * OHW;

    #pragma unroll
    for (int pi = 0; pi < 4; pi++) {
        int P = 4 * bi + pi;
        #pragma unroll
        for (int pj = 0; pj < 4; pj++) {
            int Q = 4 * bj + pj;
            float v = acc[pi][pj] * dval + np[P * OH + Q] * ns + bv;
            v = (v > 0.f) ? v : 0.2f * v;
            v *= 1.4142135623730951f;
            v = fminf(fmaxf(v, -256.f), 256.f);
            op[P * OH + Q] = v;
        }
    }
}

// ---------------------------------------------------------------------------
extern "C" void kernel_launch(void* const* d_in, const int* in_sizes, int n_in,
                              void* d_out, int out_size) {
    const float* x      = (const float*)d_in[0];
    const float* wl     = (const float*)d_in[1];
    const float* aw     = (const float*)d_in[2];
    const float* ab     = (const float*)d_in[3];
    const float* cw     = (const float*)d_in[4];
    const float* noise  = (const float*)d_in[5];
    const float* ns     = (const float*)d_in[6];
    const float* bias   = (const float*)d_in[7];
    float* out = (float*)d_out;

    style_kernel<<<B_, 512>>>(wl, aw, ab);
    prep_w_kernel<<<COUT, CIN>>>(cw);
    dcoef_kernel<<<B_, COUT>>>();
    modx_t_kernel<<<dim3(CIN / 32, HW / 32, B_), dim3(32, 8)>>>(x);
    gemm_mma_kernel<<<dim3(NTOT / BN, MTOT / BM), 256>>>();
    fuse_kernel<<<dim3(COUT, B_), 256>>>(noise, ns, bias, out);
}